// round 2
// baseline (speedup 1.0000x reference)
#include <cuda_runtime.h>

// GeometricAttention: full softmax attention, D = 144 (128 mv dims + 16 scalar dims),
// Q gets a fixed ±1 sign pattern (period 16) and scale 1/12 folded in at load.
// Flash-attention, fp32, packed fma.rn.f32x2 math.

#define BQ   64
#define BK   64
#define DTOT 144
#define NTOK 2048
#define NBH  32
#define VSTR 152   // V row stride (floats), mult of 4 for 16B-aligned double2 loads
#define SSTR 65    // S/P row stride (odd -> conflict-free row-scalar access)

__constant__ float c_ipf[16] = {1.f,1.f,-1.f,-1.f,-1.f,-1.f,-1.f,-1.f,
                                1.f,1.f, 1.f, 1.f, 1.f, 1.f,-1.f,-1.f};

__device__ __forceinline__ unsigned long long pk2(float x, float y){
    unsigned long long r;
    asm("mov.b64 %0, {%1,%2};" : "=l"(r) : "f"(x), "f"(y));
    return r;
}
__device__ __forceinline__ void fma2(unsigned long long &d,
                                     unsigned long long a, unsigned long long b){
    asm("fma.rn.f32x2 %0, %1, %2, %3;" : "=l"(d) : "l"(a), "l"(b), "l"(d));
}
__device__ __forceinline__ void mul2(unsigned long long &d, unsigned long long a){
    asm("mul.rn.f32x2 %0, %1, %2;" : "=l"(d) : "l"(d), "l"(a));
}
__device__ __forceinline__ float lo2(unsigned long long v){
    return __uint_as_float((unsigned)(v & 0xffffffffull));
}
__device__ __forceinline__ float hi2(unsigned long long v){
    return __uint_as_float((unsigned)(v >> 32));
}

extern "C" __global__ void __launch_bounds__(256, 1)
ga_kernel(const float* __restrict__ q_mv, const float* __restrict__ k_mv,
          const float* __restrict__ v_mv, const float* __restrict__ q_s,
          const float* __restrict__ k_s,  const float* __restrict__ v_s,
          float* __restrict__ out)
{
    extern __shared__ float sm[];
    float* Qs = sm;                    // [144][64] transposed+swizzled
    float* Ks = Qs + DTOT*BQ;          // [144][64] transposed+swizzled
    float* Vs = Ks + DTOT*BK;          // [64][VSTR] row-major
    float* Ss = Vs + BK*VSTR;          // [64][SSTR]
    float* Ps = Ss + BQ*SSTR;          // [64][SSTR]

    const int tid   = threadIdx.x;
    const int bh    = blockIdx.y;
    const int qbase = blockIdx.x * BQ;
    const float scale = 1.0f / 12.0f;  // 1/sqrt(144)

    // ---------------- load Q tile (transposed + swizzled, sign & scale folded) ----
    {
        const float* qm = q_mv + (long)bh * NTOK * 128;
        for (int idx = tid; idx < BQ*32; idx += 256){
            int j = idx >> 5, g = idx & 31;
            float4 v = *(const float4*)(qm + (long)(qbase + j)*128 + 4*g);
            int ib = (4*g) & 15;
            v.x *= c_ipf[ib+0]*scale; v.y *= c_ipf[ib+1]*scale;
            v.z *= c_ipf[ib+2]*scale; v.w *= c_ipf[ib+3]*scale;
            int col = (j & 3) + 4*(((j >> 2) ^ g) & 15);
            Qs[(4*g+0)*BQ + col] = v.x;  Qs[(4*g+1)*BQ + col] = v.y;
            Qs[(4*g+2)*BQ + col] = v.z;  Qs[(4*g+3)*BQ + col] = v.w;
        }
        const float* qs = q_s + (long)bh * NTOK * 16;
        for (int idx = tid; idx < BQ*4; idx += 256){
            int j = idx >> 2, g2 = idx & 3;
            float4 v = *(const float4*)(qs + (long)(qbase + j)*16 + 4*g2);
            v.x *= scale; v.y *= scale; v.z *= scale; v.w *= scale;
            int dg = 32 + g2;
            int col = (j & 3) + 4*(((j >> 2) ^ dg) & 15);
            Qs[(4*dg+0)*BQ + col] = v.x;  Qs[(4*dg+1)*BQ + col] = v.y;
            Qs[(4*dg+2)*BQ + col] = v.z;  Qs[(4*dg+3)*BQ + col] = v.w;
        }
    }

    const int qr = tid & 63;       // softmax / PV row role
    const int dc = tid >> 6;       // 0..3 -> 36-dim chunk
    const int dbase = dc * 36;
    const int ty = tid >> 4, tx = tid & 15;   // S microkernel role

    unsigned long long o2[18];
    #pragma unroll
    for (int i = 0; i < 18; i++) o2[i] = 0ull;
    float m_run = -3.0e38f, l_run = 0.0f;

    const float* km = k_mv + (long)bh * NTOK * 128;
    const float* ksc = k_s + (long)bh * NTOK * 16;
    const float* vm = v_mv + (long)bh * NTOK * 128;
    const float* vsc = v_s + (long)bh * NTOK * 16;

    for (int kt = 0; kt < NTOK/BK; kt++){
        const int kb = kt * BK;

        // -------- load K (transposed+swizzled) and V (row-major) --------
        for (int idx = tid; idx < BK*32; idx += 256){
            int j = idx >> 5, g = idx & 31;
            float4 v = *(const float4*)(km + (long)(kb + j)*128 + 4*g);
            int col = (j & 3) + 4*(((j >> 2) ^ g) & 15);
            Ks[(4*g+0)*BK + col] = v.x;  Ks[(4*g+1)*BK + col] = v.y;
            Ks[(4*g+2)*BK + col] = v.z;  Ks[(4*g+3)*BK + col] = v.w;
            float4 w = *(const float4*)(vm + (long)(kb + j)*128 + 4*g);
            *(float4*)(Vs + j*VSTR + 4*g) = w;
        }
        for (int idx = tid; idx < BK*4; idx += 256){
            int j = idx >> 2, g2 = idx & 3;
            float4 v = *(const float4*)(ksc + (long)(kb + j)*16 + 4*g2);
            int dg = 32 + g2;
            int col = (j & 3) + 4*(((j >> 2) ^ dg) & 15);
            Ks[(4*dg+0)*BK + col] = v.x;  Ks[(4*dg+1)*BK + col] = v.y;
            Ks[(4*dg+2)*BK + col] = v.z;  Ks[(4*dg+3)*BK + col] = v.w;
            float4 w = *(const float4*)(vsc + (long)(kb + j)*16 + 4*g2);
            *(float4*)(Vs + j*VSTR + 128 + 4*g2) = w;
        }
        __syncthreads();

        // -------- S = (Q scaled)^T K, 64x64, 4x4 per thread, f32x2 math --------
        {
            unsigned long long acc[4][2];
            #pragma unroll
            for (int i = 0; i < 4; i++){ acc[i][0] = 0ull; acc[i][1] = 0ull; }

            #pragma unroll 4
            for (int kk = 0; kk < DTOT; kk++){
                const int s = (kk >> 2) & 15;
                const float4  a = *(const float4*)(Qs + kk*BQ + 4*((ty ^ s) & 15));
                const double2 b = *(const double2*)(Ks + kk*BK + 4*((tx ^ s) & 15));
                unsigned long long b01 = __double_as_longlong(b.x);
                unsigned long long b23 = __double_as_longlong(b.y);
                unsigned long long a0 = pk2(a.x, a.x), a1 = pk2(a.y, a.y);
                unsigned long long a2 = pk2(a.z, a.z), a3 = pk2(a.w, a.w);
                fma2(acc[0][0], a0, b01);  fma2(acc[0][1], a0, b23);
                fma2(acc[1][0], a1, b01);  fma2(acc[1][1], a1, b23);
                fma2(acc[2][0], a2, b01);  fma2(acc[2][1], a2, b23);
                fma2(acc[3][0], a3, b01);  fma2(acc[3][1], a3, b23);
            }
            #pragma unroll
            for (int i = 0; i < 4; i++){
                float* srow = Ss + (4*ty + i)*SSTR + 4*tx;
                srow[0] = lo2(acc[i][0]);  srow[1] = hi2(acc[i][0]);
                srow[2] = lo2(acc[i][1]);  srow[3] = hi2(acc[i][1]);
            }
        }
        __syncthreads();

        // -------- online softmax (4 duplicate threads per row, identical math) ---
        {
            const float* srow = Ss + qr*SSTR;
            float mt = -3.0e38f;
            #pragma unroll 8
            for (int j = 0; j < BK; j++) mt = fmaxf(mt, srow[j]);
            float m_new = fmaxf(m_run, mt);
            float alpha = __expf(m_run - m_new);
            float sum = 0.0f;
            float* prow = Ps + qr*SSTR;
            #pragma unroll 8
            for (int j = 0; j < BK; j++){
                float p = __expf(srow[j] - m_new);
                sum += p;
                prow[j] = p;     // 4 dup threads write identical value: benign
            }
            l_run = l_run*alpha + sum;
            m_run = m_new;
            unsigned long long al2 = pk2(alpha, alpha);
            #pragma unroll
            for (int i = 0; i < 18; i++) mul2(o2[i], al2);
        }
        __syncthreads();

        // -------- O += P @ V (thread owns row qr, dims [dbase, dbase+36)) --------
        {
            const float* prow = Ps + qr*SSTR;
            #pragma unroll 4
            for (int j = 0; j < BK; j++){
                unsigned long long p2 = pk2(prow[j], prow[j]);
                const float* vrow = Vs + j*VSTR + dbase;   // uniform across warp
                #pragma unroll
                for (int g = 0; g < 9; g++){
                    double2 v = *(const double2*)(vrow + 4*g);
                    fma2(o2[2*g],   p2, __double_as_longlong(v.x));
                    fma2(o2[2*g+1], p2, __double_as_longlong(v.y));
                }
            }
        }
        __syncthreads();   // protect K/V/S/P buffers before next tile's loads
    }

    // ---------------- epilogue: O /= l, split mv / s regions ----------------
    {
        const float inv = 1.0f / l_run;
        const int n = qbase + qr;
        const long robase = (long)bh * NTOK + n;
        float* out_s_base = out + (long)NBH * NTOK * 128;
        #pragma unroll
        for (int g = 0; g < 9; g++){
            int d = dbase + 4*g;
            float4 r;
            r.x = lo2(o2[2*g])   * inv;  r.y = hi2(o2[2*g])   * inv;
            r.z = lo2(o2[2*g+1]) * inv;  r.w = hi2(o2[2*g+1]) * inv;
            if (d < 128)
                *(float4*)(out + robase*128 + d) = r;
            else
                *(float4*)(out_s_base + robase*16 + (d - 128)) = r;
        }
    }
}

extern "C" void kernel_launch(void* const* d_in, const int* in_sizes, int n_in,
                              void* d_out, int out_size)
{
    const float* q_mv = (const float*)d_in[0];
    const float* k_mv = (const float*)d_in[1];
    const float* v_mv = (const float*)d_in[2];
    const float* q_s  = (const float*)d_in[3];
    const float* k_s  = (const float*)d_in[4];
    const float* v_s  = (const float*)d_in[5];
    float* out = (float*)d_out;

    size_t smem = (size_t)(DTOT*BQ + DTOT*BK + BK*VSTR + 2*BQ*SSTR) * sizeof(float);
    cudaFuncSetAttribute(ga_kernel, cudaFuncAttributeMaxDynamicSharedMemorySize,
                         (int)smem);
    dim3 grid(NTOK/BQ, NBH);
    ga_kernel<<<grid, 256, smem>>>(q_mv, k_mv, v_mv, q_s, k_s, v_s, out);
}